// round 2
// baseline (speedup 1.0000x reference)
#include <cuda_runtime.h>
#include <cuda_bf16.h>

// Global accumulator + completion ticket (zero-initialized; reset by last CTA
// each launch so graph replays are deterministic).
__device__ float        g_accum = 0.0f;
__device__ unsigned int g_count = 0u;

// 4 segments per CTA: 512 threads = 4 groups x 128 threads, one group per segment.
#define SEGS_PER_CTA 4
#define GROUP_THREADS 128

__global__ __launch_bounds__(512) void listnet_fused_kernel(
    const float* __restrict__ mean,
    const float* __restrict__ variance,
    const float* __restrict__ targets,
    const int*   __restrict__ scope,
    float* __restrict__ out,
    int seg_len, int num_seg)
{
    const int tid     = threadIdx.x;             // 0..511
    const int grp     = tid >> 7;                // 0..3   (segment group)
    const int gtid    = tid & 127;               // 0..127 within group
    const int seg     = blockIdx.x * SEGS_PER_CTA + grp;

    float s1 = 0.0f;  // sum exp(a),  a = x + 0.5 y
    float s2 = 0.0f;  // sum exp(t)
    float s3 = 0.0f;  // sum exp(t) * b,  b = x - 0.5 y

    if (seg < num_seg) {
        const long long base = (long long)seg * seg_len;
        const float4* __restrict__ m4 = reinterpret_cast<const float4*>(mean + base);
        const float4* __restrict__ v4 = reinterpret_cast<const float4*>(variance + base);
        const float4* __restrict__ t4 = reinterpret_cast<const float4*>(targets + base);

        const int nvec = seg_len >> 2;           // float4s per segment (128 for 512)
        for (int i = gtid; i < nvec; i += GROUP_THREADS) {
            float4 m = m4[i];
            float4 v = v4[i];
            float4 t = t4[i];

            { float h = 0.5f * v.x; float a = m.x + h, b = m.x - h;
              float ea = __expf(a), et = __expf(t.x);
              s1 += ea; s2 += et; s3 += et * b; }
            { float h = 0.5f * v.y; float a = m.y + h, b = m.y - h;
              float ea = __expf(a), et = __expf(t.y);
              s1 += ea; s2 += et; s3 += et * b; }
            { float h = 0.5f * v.z; float a = m.z + h, b = m.z - h;
              float ea = __expf(a), et = __expf(t.z);
              s1 += ea; s2 += et; s3 += et * b; }
            { float h = 0.5f * v.w; float a = m.w + h, b = m.w - h;
              float ea = __expf(a), et = __expf(t.w);
              s1 += ea; s2 += et; s3 += et * b; }
        }
    }

    // Warp-level reduce of (s1, s2, s3)
    #pragma unroll
    for (int off = 16; off > 0; off >>= 1) {
        s1 += __shfl_down_sync(0xFFFFFFFFu, s1, off);
        s2 += __shfl_down_sync(0xFFFFFFFFu, s2, off);
        s3 += __shfl_down_sync(0xFFFFFFFFu, s3, off);
    }

    // Per-group (4 warps) combine in shared memory
    __shared__ float sh[SEGS_PER_CTA][4][3];     // [group][warp-in-group][3 sums]
    __shared__ float segval[SEGS_PER_CTA];
    const int warp_in_grp = gtid >> 5;
    const int lane        = gtid & 31;
    if (lane == 0) {
        sh[grp][warp_in_grp][0] = s1;
        sh[grp][warp_in_grp][1] = s2;
        sh[grp][warp_in_grp][2] = s3;
    }
    __syncthreads();

    if (gtid == 0) {
        float S1 = sh[grp][0][0] + sh[grp][1][0] + sh[grp][2][0] + sh[grp][3][0];
        float S2 = sh[grp][0][1] + sh[grp][1][1] + sh[grp][2][1] + sh[grp][3][1];
        float S3 = sh[grp][0][2] + sh[grp][1][2] + sh[grp][2][2] + sh[grp][3][2];
        float val = 0.0f;
        if (seg < num_seg) {
            // per_seg = (log(S1) - S3/S2) / scope[seg]
            val = (logf(S1) - S3 / S2) / (float)scope[seg];
        }
        segval[grp] = val;
    }
    __syncthreads();

    if (tid == 0) {
        float cta_sum = segval[0] + segval[1] + segval[2] + segval[3];
        atomicAdd(&g_accum, cta_sum);
        __threadfence();
        unsigned int done = atomicAdd(&g_count, 1u);
        if (done == gridDim.x - 1u) {
            // All CTA contributions visible; finalize and reset for next replay.
            out[0] = g_accum / (float)num_seg;
            g_accum = 0.0f;
            g_count = 0u;
        }
    }
}

extern "C" void kernel_launch(void* const* d_in, const int* in_sizes, int n_in,
                              void* d_out, int out_size)
{
    // metadata order: mean (N), variance (N), scope (NUM_SEG), targets (N)
    const float* mean     = (const float*)d_in[0];
    const float* variance = (const float*)d_in[1];
    const int*   scope    = (const int*)  d_in[2];
    const float* targets  = (const float*)d_in[3];
    float* out = (float*)d_out;

    const int n       = in_sizes[0];
    const int num_seg = in_sizes[2];
    const int seg_len = n / num_seg;   // 512 for this dataset

    const int grid = (num_seg + SEGS_PER_CTA - 1) / SEGS_PER_CTA;
    listnet_fused_kernel<<<grid, 512>>>(mean, variance, targets, scope, out,
                                        seg_len, num_seg);
}